// round 7
// baseline (speedup 1.0000x reference)
#include <cuda_runtime.h>
#include <cuda_bf16.h>
#include <cstdint>

// Problem constants (B=2, S=1024, H=32, KVH=8, HD=128, DM=4096)
#define T_TOK   2048
#define DMODEL  4096
#define QKVC    6144
#define NH      32
#define NKV     8
#define HDIM    128
#define SEQ     1024
#define NBATCH  2
#define QSCALE  0.08838834764831845f

__device__ float g_qkv[(size_t)T_TOK * QKVC];
__device__ uint32_t g_pa[(size_t)T_TOK * DMODEL];   // packed tf32 A tiles
__device__ uint32_t g_pb[(size_t)QKVC * DMODEL];    // packed tf32 W tiles

__device__ __forceinline__ uint32_t f2tf32(float x) {
    uint32_t u;
    asm("cvt.rna.tf32.f32 %0, %1;" : "=r"(u) : "f"(x));
    return u;
}

#define MMA_TF32(d, a, b)                                                     \
    asm volatile(                                                             \
        "mma.sync.aligned.m16n8k8.row.col.f32.tf32.tf32.f32 "                 \
        "{%0,%1,%2,%3},{%4,%5,%6,%7},{%8,%9},{%0,%1,%2,%3};"                  \
        : "+f"(d[0]), "+f"(d[1]), "+f"(d[2]), "+f"(d[3])                      \
        : "r"(a[0]), "r"(a[1]), "r"(a[2]), "r"(a[3]), "r"(b[0]), "r"(b[1]))

__device__ __forceinline__ void cp_async16(uint32_t smem_addr, const void* gptr) {
    asm volatile("cp.async.cg.shared.global [%0], [%1], 16;"
                 :: "r"(smem_addr), "l"(gptr) : "memory");
}
#define CP_COMMIT() asm volatile("cp.async.commit_group;" ::: "memory")
#define CP_WAIT2()  asm volatile("cp.async.wait_group 2;" ::: "memory")

// ---------------------------------------------------------------------------
// Kernel 0a: pack A [2048,4096] fp32 -> g_pa tf32 fragment-major tiles.
// ---------------------------------------------------------------------------
__global__ __launch_bounds__(256) void pack_a_kernel(const float* __restrict__ A) {
    int i = blockIdx.x * 256 + threadIdx.x;
    int r  = i >> 10;
    int k0 = (i & 1023) << 2;
    float4 v = *reinterpret_cast<const float4*>(A + (size_t)r * DMODEL + k0);

    int mTile = r >> 7, rLoc = r & 127;
    int kTile = k0 >> 4, kLoc = k0 & 15;
    uint32_t* dst = g_pa + ((size_t)(mTile * (DMODEL / 16) + kTile)) * 2048;

    int ks  = kLoc >> 3;
    int kc0 = kLoc & 7;
    int rb  = rLoc >> 4, r16 = rLoc & 15;
    int reg = ((kc0 >= 4) ? 2 : 0) + ((r16 >= 8) ? 1 : 0);
    int base = ((ks << 3) + rb) << 7;
    int lane0 = (r16 & 7) << 2;
    float a[4] = {v.x, v.y, v.z, v.w};
#pragma unroll
    for (int j = 0; j < 4; j++)
        dst[base + ((lane0 + j) << 2) + reg] = f2tf32(a[j]);
}

// ---------------------------------------------------------------------------
// Kernel 0b: pack W [4096,6144] fp32 -> g_pb tf32 fragment-major tiles.
// ---------------------------------------------------------------------------
__global__ __launch_bounds__(256) void pack_w_kernel(const float* __restrict__ W) {
    int i = blockIdx.x * 256 + threadIdx.x;
    int k  = i / 1536;
    int n0 = (i - k * 1536) << 2;
    float4 v = *reinterpret_cast<const float4*>(W + (size_t)k * QKVC + n0);

    int nTile = n0 >> 7, nLoc0 = n0 & 127;
    int kTile = k >> 4,  kLoc  = k & 15;
    uint32_t* dst = g_pb + ((size_t)(nTile * (DMODEL / 16) + kTile)) * 2048;

    int ks = kLoc >> 3, kc = kLoc & 7;
    int kl = kc & 3, rg = kc >> 2;
    float a[4] = {v.x, v.y, v.z, v.w};
#pragma unroll
    for (int j = 0; j < 4; j++) {
        int n = nLoc0 + j;
        int nblk = n >> 3, nn = n & 7;
        dst[((ks << 4) + nblk) * 64 + (((nn << 2) + kl) << 1) + rg] = f2tf32(a[j]);
    }
}

// ---------------------------------------------------------------------------
// Kernel 1: QKV GEMM, tf32 mma.sync, pre-packed operands, cp.async 4-stage.
// CTA tile 256x128, 512 threads (16 warps as 4x4), warp tile 64x32.
// Stage = 24KB (two 128x16 A tiles + one 128x16 B tile); 4 stages = 96KB.
// ---------------------------------------------------------------------------
__global__ __launch_bounds__(512, 1) void gemm_tf32_kernel() {
    extern __shared__ __align__(16) uint32_t smem[];   // 4 * 6144 words

    const int tid  = threadIdx.x;
    const int wid  = tid >> 5;
    const int lane = tid & 31;
    const int gid  = lane >> 2;
    const int tig  = lane & 3;
    const int wm   = wid >> 2;        // 0..3 (M)
    const int wn   = wid & 3;         // 0..3 (N)

    const uint32_t smem_base = (uint32_t)__cvta_generic_to_shared(smem);
    const int m0 = blockIdx.y * 2;                      // two stacked 128-row A tiles
    const uint32_t* pa0 = g_pa + (size_t)(m0)     * (DMODEL / 16) * 2048;
    const uint32_t* pa1 = g_pa + (size_t)(m0 + 1) * (DMODEL / 16) * 2048;
    const uint32_t* pb  = g_pb + (size_t)blockIdx.x * (DMODEL / 16) * 2048;

    const int NTILES = DMODEL / 16;   // 256

#define ISSUE(kt, s)                                                           \
    do {                                                                       \
        uint32_t sa = smem_base + (uint32_t)(s) * 24576;                       \
        const uint32_t* gA0 = pa0 + (size_t)(kt) * 2048 + tid * 4;             \
        const uint32_t* gA1 = pa1 + (size_t)(kt) * 2048 + tid * 4;             \
        const uint32_t* gB  = pb  + (size_t)(kt) * 2048 + tid * 4;             \
        cp_async16(sa + tid * 16,          gA0);                               \
        cp_async16(sa + 8192 + tid * 16,   gA1);                               \
        cp_async16(sa + 16384 + tid * 16,  gB);                                \
    } while (0)

    float acc[4][4][4];
#pragma unroll
    for (int i = 0; i < 4; i++)
#pragma unroll
        for (int j = 0; j < 4; j++)
#pragma unroll
            for (int c = 0; c < 4; c++) acc[i][j][c] = 0.f;

    ISSUE(0, 0); CP_COMMIT();
    ISSUE(1, 1); CP_COMMIT();
    ISSUE(2, 2); CP_COMMIT();
    CP_WAIT2();
    __syncthreads();

    for (int kt = 0; kt < NTILES; kt++) {
        if (kt + 3 < NTILES) ISSUE(kt + 3, (kt + 3) & 3);
        CP_COMMIT();

        // Warp's A sub-tile: wm>>1 selects 128-row tile, (wm&1)*4 the row-block base.
        const uint32_t* As = smem + (size_t)(kt & 3) * 6144 + (size_t)(wm >> 1) * 2048;
        const uint32_t* Bs = smem + (size_t)(kt & 3) * 6144 + 4096;
        const int rbBase = (wm & 1) << 2;

#pragma unroll
        for (int ks = 0; ks < 2; ks++) {
            uint4 av[4];
            uint2 bv[4];
#pragma unroll
            for (int i = 0; i < 4; i++)
                av[i] = *reinterpret_cast<const uint4*>(
                    &As[(((ks << 3) + rbBase + i) << 7) + (lane << 2)]);
#pragma unroll
            for (int j = 0; j < 4; j++)
                bv[j] = *reinterpret_cast<const uint2*>(
                    &Bs[(((ks << 4) + (wn << 2) + j) << 6) + (lane << 1)]);
#pragma unroll
            for (int i = 0; i < 4; i++)
#pragma unroll
                for (int j = 0; j < 4; j++)
                    MMA_TF32(acc[i][j], (reinterpret_cast<uint32_t*>(&av[i])),
                             (reinterpret_cast<uint32_t*>(&bv[j])));
        }

        CP_WAIT2();
        __syncthreads();
    }

    // Epilogue.
    float* C = g_qkv + (size_t)blockIdx.y * 256 * QKVC + blockIdx.x * 128;
#pragma unroll
    for (int i = 0; i < 4; i++) {
#pragma unroll
        for (int j = 0; j < 4; j++) {
            int r = wm * 64 + i * 16 + gid;
            int c = wn * 32 + j * 8 + 2 * tig;
            float2 v0 = {acc[i][j][0], acc[i][j][1]};
            float2 v1 = {acc[i][j][2], acc[i][j][3]};
            *reinterpret_cast<float2*>(C + (size_t)(r)     * QKVC + c) = v0;
            *reinterpret_cast<float2*>(C + (size_t)(r + 8) * QKVC + c) = v1;
        }
    }
}

// ---------------------------------------------------------------------------
// Kernel 2: RoPE in-place (q scaled by 1/sqrt(HD)).
// ---------------------------------------------------------------------------
__global__ __launch_bounds__(256) void rope_kernel(const float* __restrict__ cosT,
                                                   const float* __restrict__ sinT) {
    int idx = blockIdx.x * 256 + threadIdx.x;
    int d    = idx & 63;
    int head = (idx >> 6) % 40;
    int t    = idx / (64 * 40);

    float c = cosT[t * HDIM + d];
    float s = sinT[t * HDIM + d];

    float* p = g_qkv + (size_t)t * QKVC + head * HDIM;
    float x1 = p[d];
    float x2 = p[d + 64];
    float o1 = x1 * c - x2 * s;
    float o2 = x2 * c + x1 * s;
    if (head < NH) { o1 *= QSCALE; o2 *= QSCALE; }
    p[d]      = o1;
    p[d + 64] = o2;
}

// ---------------------------------------------------------------------------
// Kernel 3: tensor-core flash attention (causal, GQA n_rep=4), tf32 mma.
// (unchanged from R6 best)
// ---------------------------------------------------------------------------
#define QS_STR 132
#define KS_STR 132
#define VS_STR 136
#define PS_STR 68
#define QS_WORDS (128 * QS_STR)
#define KS_WORDS (64 * KS_STR)
#define VS_WORDS (64 * VS_STR)
#define PS_WORDS (128 * PS_STR)
#define ATTN_SMEM ((QS_WORDS + KS_WORDS + VS_WORDS + PS_WORDS) * 4)

__global__ __launch_bounds__(256, 1) void attn_tc_kernel(float* __restrict__ out) {
    extern __shared__ __align__(16) uint32_t sm[];
    uint32_t* Qs = sm;
    uint32_t* Ks = Qs + QS_WORDS;
    uint32_t* Vs = Ks + KS_WORDS;
    uint32_t* Ps = Vs + VS_WORDS;

    const int tid  = threadIdx.x;
    const int wid  = tid >> 5;
    const int lane = tid & 31;
    const int gid  = lane >> 2;
    const int tig  = lane & 3;
    const int qrow = wid * 16;

    const int b   = blockIdx.y >> 5;
    const int h   = blockIdx.y & 31;
    const int kvh = h >> 2;
    const int q0  = blockIdx.x * 128;

    const float* Qg = g_qkv + (size_t)(b * SEQ + q0) * QKVC + h * HDIM;
    const float* Kg = g_qkv + (size_t)(b * SEQ) * QKVC + NH * HDIM + kvh * HDIM;
    const float* Vg = Kg + NKV * HDIM;

#pragma unroll
    for (int i = 0; i < 16; i++) {
        int idx = tid + i * 256;
        int r = idx >> 5;
        int c = (idx & 31) << 2;
        float4 v = *reinterpret_cast<const float4*>(Qg + (size_t)r * QKVC + c);
        uint32_t* d = &Qs[r * QS_STR + c];
        d[0] = f2tf32(v.x); d[1] = f2tf32(v.y); d[2] = f2tf32(v.z); d[3] = f2tf32(v.w);
    }

    float m[2] = {-1e30f, -1e30f}, l[2] = {0.f, 0.f};
    float oacc[16][4];
#pragma unroll
    for (int nb = 0; nb < 16; nb++)
#pragma unroll
        for (int c = 0; c < 4; c++) oacc[nb][c] = 0.f;

    const int ktiles = 2 * (blockIdx.x + 1);
    for (int kt = 0; kt < ktiles; kt++) {
        const int kv0 = kt * 64;
        __syncthreads();
#pragma unroll
        for (int i = 0; i < 8; i++) {
            int idx = tid + i * 256;
            int r = idx >> 5;
            int c = (idx & 31) << 2;
            float4 kv = *reinterpret_cast<const float4*>(Kg + (size_t)(kv0 + r) * QKVC + c);
            float4 vv = *reinterpret_cast<const float4*>(Vg + (size_t)(kv0 + r) * QKVC + c);
            uint32_t* dk = &Ks[r * KS_STR + c];
            dk[0] = f2tf32(kv.x); dk[1] = f2tf32(kv.y); dk[2] = f2tf32(kv.z); dk[3] = f2tf32(kv.w);
            uint32_t* dv = &Vs[r * VS_STR + c];
            dv[0] = f2tf32(vv.x); dv[1] = f2tf32(vv.y); dv[2] = f2tf32(vv.z); dv[3] = f2tf32(vv.w);
        }
        __syncthreads();

        float sacc[8][4];
#pragma unroll
        for (int nb = 0; nb < 8; nb++)
#pragma unroll
            for (int c = 0; c < 4; c++) sacc[nb][c] = 0.f;

#pragma unroll
        for (int ks = 0; ks < 16; ks++) {
            const int k0 = ks * 8;
            uint32_t a[4];
            a[0] = Qs[(qrow + gid)     * QS_STR + k0 + tig];
            a[1] = Qs[(qrow + gid + 8) * QS_STR + k0 + tig];
            a[2] = Qs[(qrow + gid)     * QS_STR + k0 + tig + 4];
            a[3] = Qs[(qrow + gid + 8) * QS_STR + k0 + tig + 4];
#pragma unroll
            for (int nb = 0; nb < 8; nb++) {
                uint32_t bb[2];
                bb[0] = Ks[(nb * 8 + gid) * KS_STR + k0 + tig];
                bb[1] = Ks[(nb * 8 + gid) * KS_STR + k0 + tig + 4];
                MMA_TF32(sacc[nb], a, bb);
            }
        }

        const int row0 = q0 + qrow + gid;
        const int row1 = row0 + 8;
        if (kv0 + 63 > row0) {
#pragma unroll
            for (int nb = 0; nb < 8; nb++) {
                int c0 = kv0 + nb * 8 + 2 * tig;
                if (c0 > row0)     sacc[nb][0] = -1e30f;
                if (c0 + 1 > row0) sacc[nb][1] = -1e30f;
                if (c0 > row1)     sacc[nb][2] = -1e30f;
                if (c0 + 1 > row1) sacc[nb][3] = -1e30f;
            }
        }

#pragma unroll
        for (int r = 0; r < 2; r++) {
            float rmax = -1e30f;
#pragma unroll
            for (int nb = 0; nb < 8; nb++)
                rmax = fmaxf(rmax, fmaxf(sacc[nb][2 * r], sacc[nb][2 * r + 1]));
            rmax = fmaxf(rmax, __shfl_xor_sync(0xffffffffu, rmax, 1));
            rmax = fmaxf(rmax, __shfl_xor_sync(0xffffffffu, rmax, 2));
            float nm = fmaxf(m[r], rmax);
            float corr = __expf(m[r] - nm);
            float rs = 0.f;
#pragma unroll
            for (int nb = 0; nb < 8; nb++) {
                float p0 = __expf(sacc[nb][2 * r]     - nm);
                float p1 = __expf(sacc[nb][2 * r + 1] - nm);
                sacc[nb][2 * r] = p0; sacc[nb][2 * r + 1] = p1;
                rs += p0 + p1;
            }
            rs += __shfl_xor_sync(0xffffffffu, rs, 1);
            rs += __shfl_xor_sync(0xffffffffu, rs, 2);
            m[r] = nm;
            l[r] = l[r] * corr + rs;
#pragma unroll
            for (int nb = 0; nb < 16; nb++) {
                oacc[nb][2 * r]     *= corr;
                oacc[nb][2 * r + 1] *= corr;
            }
        }

#pragma unroll
        for (int nb = 0; nb < 8; nb++) {
            int c = nb * 8 + 2 * tig;
            Ps[(qrow + gid)     * PS_STR + c]     = f2tf32(sacc[nb][0]);
            Ps[(qrow + gid)     * PS_STR + c + 1] = f2tf32(sacc[nb][1]);
            Ps[(qrow + gid + 8) * PS_STR + c]     = f2tf32(sacc[nb][2]);
            Ps[(qrow + gid + 8) * PS_STR + c + 1] = f2tf32(sacc[nb][3]);
        }

#pragma unroll
        for (int kb = 0; kb < 8; kb++) {
            const int k0 = kb * 8;
            uint32_t a[4];
            a[0] = Ps[(qrow + gid)     * PS_STR + k0 + tig];
            a[1] = Ps[(qrow + gid + 8) * PS_STR + k0 + tig];
            a[2] = Ps[(qrow + gid)     * PS_STR + k0 + tig + 4];
            a[3] = Ps[(qrow + gid + 8) * PS_STR + k0 + tig + 4];
#pragma unroll
            for (int nb = 0; nb < 16; nb++) {
                uint32_t bb[2];
                bb[0] = Vs[(k0 + tig)     * VS_STR + nb * 8 + gid];
                bb[1] = Vs[(k0 + tig + 4) * VS_STR + nb * 8 + gid];
                MMA_TF32(oacc[nb], a, bb);
            }
        }
    }

    const float inv0 = 1.f / l[0];
    const float inv1 = 1.f / l[1];
    const int t0 = b * SEQ + q0 + qrow + gid;
#pragma unroll
    for (int nb = 0; nb < 16; nb++) {
        int c = nb * 8 + 2 * tig;
        float2 v0 = {oacc[nb][0] * inv0, oacc[nb][1] * inv0};
        float2 v1 = {oacc[nb][2] * inv1, oacc[nb][3] * inv1};
        *reinterpret_cast<float2*>(out + (size_t)t0 * (NH * HDIM) + h * HDIM + c) = v0;
        *reinterpret_cast<float2*>(out + (size_t)(t0 + 8) * (NH * HDIM) + h * HDIM + c) = v1;
    }
}

// ---------------------------------------------------------------------------
extern "C" void kernel_launch(void* const* d_in, const int* in_sizes, int n_in,
                              void* d_out, int out_size) {
    const float* hidden = (const float*)d_in[0];
    const float* w_qkv  = (const float*)d_in[1];
    const float* cosT   = (const float*)d_in[2];
    const float* sinT   = (const float*)d_in[3];
    float* out = (float*)d_out;

    cudaFuncSetAttribute(gemm_tf32_kernel, cudaFuncAttributeMaxDynamicSharedMemorySize, 98304);
    cudaFuncSetAttribute(attn_tc_kernel, cudaFuncAttributeMaxDynamicSharedMemorySize, ATTN_SMEM);

    pack_a_kernel<<<(T_TOK * DMODEL / 4) / 256, 256>>>(hidden);
    pack_w_kernel<<<(DMODEL * QKVC / 4) / 256, 256>>>(w_qkv);

    dim3 ggrid(QKVC / 128, T_TOK / 256);   // (48, 8)
    gemm_tf32_kernel<<<ggrid, 512, 98304>>>();

    int rope_threads = T_TOK * (NH + NKV) * 64;
    rope_kernel<<<rope_threads / 256, 256>>>(cosT, sinT);

    dim3 agrid(SEQ / 128, NBATCH * NH);    // (8, 64)
    attn_tc_kernel<<<agrid, 256, ATTN_SMEM>>>(out);
}

// round 8
// speedup vs baseline: 1.1661x; 1.1661x over previous
#include <cuda_runtime.h>
#include <cuda_bf16.h>
#include <cstdint>

// Problem constants (B=2, S=1024, H=32, KVH=8, HD=128, DM=4096)
#define T_TOK   2048
#define DMODEL  4096
#define QKVC    6144
#define NH      32
#define NKV     8
#define HDIM    128
#define SEQ     1024
#define NBATCH  2
#define QSCALE  0.08838834764831845f

__device__ float g_qkv[(size_t)T_TOK * QKVC];
__device__ uint32_t g_pa[(size_t)T_TOK * DMODEL];   // packed tf32 A tiles
__device__ uint32_t g_pb[(size_t)QKVC * DMODEL];    // packed tf32 W tiles

__device__ __forceinline__ uint32_t f2tf32(float x) {
    uint32_t u;
    asm("cvt.rna.tf32.f32 %0, %1;" : "=r"(u) : "f"(x));
    return u;
}

#define MMA_TF32(d, a, b)                                                     \
    asm volatile(                                                             \
        "mma.sync.aligned.m16n8k8.row.col.f32.tf32.tf32.f32 "                 \
        "{%0,%1,%2,%3},{%4,%5,%6,%7},{%8,%9},{%0,%1,%2,%3};"                  \
        : "+f"(d[0]), "+f"(d[1]), "+f"(d[2]), "+f"(d[3])                      \
        : "r"(a[0]), "r"(a[1]), "r"(a[2]), "r"(a[3]), "r"(b[0]), "r"(b[1]))

__device__ __forceinline__ void cp_async16(uint32_t smem_addr, const void* gptr) {
    asm volatile("cp.async.cg.shared.global [%0], [%1], 16;"
                 :: "r"(smem_addr), "l"(gptr) : "memory");
}
#define CP_COMMIT() asm volatile("cp.async.commit_group;" ::: "memory")
#define CP_WAIT1()  asm volatile("cp.async.wait_group 1;" ::: "memory")

// ---------------------------------------------------------------------------
// Kernel 0a: pack A [2048,4096] fp32 -> g_pa tf32 fragment-major tiles.
// ---------------------------------------------------------------------------
__global__ __launch_bounds__(256) void pack_a_kernel(const float* __restrict__ A) {
    int i = blockIdx.x * 256 + threadIdx.x;
    int r  = i >> 10;
    int k0 = (i & 1023) << 2;
    float4 v = *reinterpret_cast<const float4*>(A + (size_t)r * DMODEL + k0);

    int mTile = r >> 7, rLoc = r & 127;
    int kTile = k0 >> 4, kLoc = k0 & 15;
    uint32_t* dst = g_pa + ((size_t)(mTile * (DMODEL / 16) + kTile)) * 2048;

    int ks  = kLoc >> 3;
    int kc0 = kLoc & 7;
    int rb  = rLoc >> 4, r16 = rLoc & 15;
    int reg = ((kc0 >= 4) ? 2 : 0) + ((r16 >= 8) ? 1 : 0);
    int base = ((ks << 3) + rb) << 7;
    int lane0 = (r16 & 7) << 2;
    float a[4] = {v.x, v.y, v.z, v.w};
#pragma unroll
    for (int j = 0; j < 4; j++)
        dst[base + ((lane0 + j) << 2) + reg] = f2tf32(a[j]);
}

// ---------------------------------------------------------------------------
// Kernel 0b: pack W [4096,6144] fp32 -> g_pb tf32 fragment-major tiles.
// ---------------------------------------------------------------------------
__global__ __launch_bounds__(256) void pack_w_kernel(const float* __restrict__ W) {
    int i = blockIdx.x * 256 + threadIdx.x;
    int k  = i / 1536;
    int n0 = (i - k * 1536) << 2;
    float4 v = *reinterpret_cast<const float4*>(W + (size_t)k * QKVC + n0);

    int nTile = n0 >> 7, nLoc0 = n0 & 127;
    int kTile = k >> 4,  kLoc  = k & 15;
    uint32_t* dst = g_pb + ((size_t)(nTile * (DMODEL / 16) + kTile)) * 2048;

    int ks = kLoc >> 3, kc = kLoc & 7;
    int kl = kc & 3, rg = kc >> 2;
    float a[4] = {v.x, v.y, v.z, v.w};
#pragma unroll
    for (int j = 0; j < 4; j++) {
        int n = nLoc0 + j;
        int nblk = n >> 3, nn = n & 7;
        dst[((ks << 4) + nblk) * 64 + (((nn << 2) + kl) << 1) + rg] = f2tf32(a[j]);
    }
}

// ---------------------------------------------------------------------------
// Kernel 1: QKV GEMM, tf32 mma.sync, pre-packed operands.
// CTA 128x128, 256 threads (8 warps 2x4), warp tile 64x32.  (R6 shape)
// Stage = BK 32 = two packed kTiles of A + two of B = 32KB; 3 stages = 96KB.
// 128 iterations -> half the barriers of the BK16 version.
// ---------------------------------------------------------------------------
__global__ __launch_bounds__(256, 2) void gemm_tf32_kernel() {
    extern __shared__ __align__(16) uint32_t smem[];   // 3 * 8192 words

    const int tid  = threadIdx.x;
    const int wid  = tid >> 5;
    const int lane = tid & 31;
    const int gid  = lane >> 2;
    const int tig  = lane & 3;
    const int wm   = wid >> 2;
    const int wn   = wid & 3;

    const uint32_t smem_base = (uint32_t)__cvta_generic_to_shared(smem);
    const uint32_t* pa = g_pa + (size_t)blockIdx.y * (DMODEL / 16) * 2048;
    const uint32_t* pb = g_pb + (size_t)blockIdx.x * (DMODEL / 16) * 2048;

    const int NCH = DMODEL / 32;   // 128 BK32 chunks

    // Stage layout (words): [A ktile0 2048][A ktile1 2048][B ktile0 2048][B ktile1 2048]
#define ISSUE(ch, s)                                                           \
    do {                                                                       \
        uint32_t sa = smem_base + (uint32_t)(s) * 32768;                       \
        const uint32_t* gA = pa + (size_t)(ch) * 4096 + tid * 4;               \
        const uint32_t* gB = pb + (size_t)(ch) * 4096 + tid * 4;               \
        cp_async16(sa + tid * 16,           gA);                               \
        cp_async16(sa + tid * 16 + 4096,    gA + 1024);                        \
        cp_async16(sa + tid * 16 + 8192,    gA + 2048);                        \
        cp_async16(sa + tid * 16 + 12288,   gA + 3072);                        \
        cp_async16(sa + 16384 + tid * 16,         gB);                         \
        cp_async16(sa + 16384 + tid * 16 + 4096,  gB + 1024);                  \
        cp_async16(sa + 16384 + tid * 16 + 8192,  gB + 2048);                  \
        cp_async16(sa + 16384 + tid * 16 + 12288, gB + 3072);                  \
    } while (0)

    float acc[4][4][4];
#pragma unroll
    for (int i = 0; i < 4; i++)
#pragma unroll
        for (int j = 0; j < 4; j++)
#pragma unroll
            for (int c = 0; c < 4; c++) acc[i][j][c] = 0.f;

    // Prologue: stages 0,1.
    ISSUE(0, 0); CP_COMMIT();
    ISSUE(1, 1); CP_COMMIT();
    CP_WAIT1();            // stage 0 resident
    __syncthreads();

    for (int ch = 0; ch < NCH; ch++) {
        // Refill the stage freed at the end of the previous iteration.
        if (ch + 2 < NCH) ISSUE(ch + 2, (ch + 2) % 3);
        CP_COMMIT();

        const uint32_t* St = smem + (size_t)(ch % 3) * 8192;

#pragma unroll
        for (int ks4 = 0; ks4 < 4; ks4++) {
            const uint32_t* As = St + ((ks4 >> 1) ? 2048 : 0);
            const uint32_t* Bs = St + 4096 + ((ks4 >> 1) ? 2048 : 0);
            const int ks = ks4 & 1;
            uint4 av[4];
            uint2 bv[4];
#pragma unroll
            for (int i = 0; i < 4; i++)
                av[i] = *reinterpret_cast<const uint4*>(
                    &As[(((ks << 3) + (wm << 2) + i) << 7) + (lane << 2)]);
#pragma unroll
            for (int j = 0; j < 4; j++)
                bv[j] = *reinterpret_cast<const uint2*>(
                    &Bs[(((ks << 4) + (wn << 2) + j) << 6) + (lane << 1)]);
#pragma unroll
            for (int i = 0; i < 4; i++)
#pragma unroll
                for (int j = 0; j < 4; j++)
                    MMA_TF32(acc[i][j], (reinterpret_cast<uint32_t*>(&av[i])),
                             (reinterpret_cast<uint32_t*>(&bv[j])));
        }

        CP_WAIT1();        // next stage's data resident
        __syncthreads();   // all warps done reading current stage
    }

    // Epilogue.
    float* C = g_qkv + (size_t)blockIdx.y * 128 * QKVC + blockIdx.x * 128;
#pragma unroll
    for (int i = 0; i < 4; i++) {
#pragma unroll
        for (int j = 0; j < 4; j++) {
            int r = wm * 64 + i * 16 + gid;
            int c = wn * 32 + j * 8 + 2 * tig;
            float2 v0 = {acc[i][j][0], acc[i][j][1]};
            float2 v1 = {acc[i][j][2], acc[i][j][3]};
            *reinterpret_cast<float2*>(C + (size_t)(r)     * QKVC + c) = v0;
            *reinterpret_cast<float2*>(C + (size_t)(r + 8) * QKVC + c) = v1;
        }
    }
}

// ---------------------------------------------------------------------------
// Kernel 2: RoPE in-place (q scaled by 1/sqrt(HD)).
// ---------------------------------------------------------------------------
__global__ __launch_bounds__(256) void rope_kernel(const float* __restrict__ cosT,
                                                   const float* __restrict__ sinT) {
    int idx = blockIdx.x * 256 + threadIdx.x;
    int d    = idx & 63;
    int head = (idx >> 6) % 40;
    int t    = idx / (64 * 40);

    float c = cosT[t * HDIM + d];
    float s = sinT[t * HDIM + d];

    float* p = g_qkv + (size_t)t * QKVC + head * HDIM;
    float x1 = p[d];
    float x2 = p[d + 64];
    float o1 = x1 * c - x2 * s;
    float o2 = x2 * c + x1 * s;
    if (head < NH) { o1 *= QSCALE; o2 *= QSCALE; }
    p[d]      = o1;
    p[d + 64] = o2;
}

// ---------------------------------------------------------------------------
// Kernel 3: tensor-core flash attention (causal, GQA n_rep=4), tf32 mma.
// (unchanged from R6 best)
// ---------------------------------------------------------------------------
#define QS_STR 132
#define KS_STR 132
#define VS_STR 136
#define PS_STR 68
#define QS_WORDS (128 * QS_STR)
#define KS_WORDS (64 * KS_STR)
#define VS_WORDS (64 * VS_STR)
#define PS_WORDS (128 * PS_STR)
#define ATTN_SMEM ((QS_WORDS + KS_WORDS + VS_WORDS + PS_WORDS) * 4)

__global__ __launch_bounds__(256, 1) void attn_tc_kernel(float* __restrict__ out) {
    extern __shared__ __align__(16) uint32_t sm[];
    uint32_t* Qs = sm;
    uint32_t* Ks = Qs + QS_WORDS;
    uint32_t* Vs = Ks + KS_WORDS;
    uint32_t* Ps = Vs + VS_WORDS;

    const int tid  = threadIdx.x;
    const int wid  = tid >> 5;
    const int lane = tid & 31;
    const int gid  = lane >> 2;
    const int tig  = lane & 3;
    const int qrow = wid * 16;

    const int b   = blockIdx.y >> 5;
    const int h   = blockIdx.y & 31;
    const int kvh = h >> 2;
    const int q0  = blockIdx.x * 128;

    const float* Qg = g_qkv + (size_t)(b * SEQ + q0) * QKVC + h * HDIM;
    const float* Kg = g_qkv + (size_t)(b * SEQ) * QKVC + NH * HDIM + kvh * HDIM;
    const float* Vg = Kg + NKV * HDIM;

#pragma unroll
    for (int i = 0; i < 16; i++) {
        int idx = tid + i * 256;
        int r = idx >> 5;
        int c = (idx & 31) << 2;
        float4 v = *reinterpret_cast<const float4*>(Qg + (size_t)r * QKVC + c);
        uint32_t* d = &Qs[r * QS_STR + c];
        d[0] = f2tf32(v.x); d[1] = f2tf32(v.y); d[2] = f2tf32(v.z); d[3] = f2tf32(v.w);
    }

    float m[2] = {-1e30f, -1e30f}, l[2] = {0.f, 0.f};
    float oacc[16][4];
#pragma unroll
    for (int nb = 0; nb < 16; nb++)
#pragma unroll
        for (int c = 0; c < 4; c++) oacc[nb][c] = 0.f;

    const int ktiles = 2 * (blockIdx.x + 1);
    for (int kt = 0; kt < ktiles; kt++) {
        const int kv0 = kt * 64;
        __syncthreads();
#pragma unroll
        for (int i = 0; i < 8; i++) {
            int idx = tid + i * 256;
            int r = idx >> 5;
            int c = (idx & 31) << 2;
            float4 kv = *reinterpret_cast<const float4*>(Kg + (size_t)(kv0 + r) * QKVC + c);
            float4 vv = *reinterpret_cast<const float4*>(Vg + (size_t)(kv0 + r) * QKVC + c);
            uint32_t* dk = &Ks[r * KS_STR + c];
            dk[0] = f2tf32(kv.x); dk[1] = f2tf32(kv.y); dk[2] = f2tf32(kv.z); dk[3] = f2tf32(kv.w);
            uint32_t* dv = &Vs[r * VS_STR + c];
            dv[0] = f2tf32(vv.x); dv[1] = f2tf32(vv.y); dv[2] = f2tf32(vv.z); dv[3] = f2tf32(vv.w);
        }
        __syncthreads();

        float sacc[8][4];
#pragma unroll
        for (int nb = 0; nb < 8; nb++)
#pragma unroll
            for (int c = 0; c < 4; c++) sacc[nb][c] = 0.f;

#pragma unroll
        for (int ks = 0; ks < 16; ks++) {
            const int k0 = ks * 8;
            uint32_t a[4];
            a[0] = Qs[(qrow + gid)     * QS_STR + k0 + tig];
            a[1] = Qs[(qrow + gid + 8) * QS_STR + k0 + tig];
            a[2] = Qs[(qrow + gid)     * QS_STR + k0 + tig + 4];
            a[3] = Qs[(qrow + gid + 8) * QS_STR + k0 + tig + 4];
#pragma unroll
            for (int nb = 0; nb < 8; nb++) {
                uint32_t bb[2];
                bb[0] = Ks[(nb * 8 + gid) * KS_STR + k0 + tig];
                bb[1] = Ks[(nb * 8 + gid) * KS_STR + k0 + tig + 4];
                MMA_TF32(sacc[nb], a, bb);
            }
        }

        const int row0 = q0 + qrow + gid;
        const int row1 = row0 + 8;
        if (kv0 + 63 > row0) {
#pragma unroll
            for (int nb = 0; nb < 8; nb++) {
                int c0 = kv0 + nb * 8 + 2 * tig;
                if (c0 > row0)     sacc[nb][0] = -1e30f;
                if (c0 + 1 > row0) sacc[nb][1] = -1e30f;
                if (c0 > row1)     sacc[nb][2] = -1e30f;
                if (c0 + 1 > row1) sacc[nb][3] = -1e30f;
            }
        }

#pragma unroll
        for (int r = 0; r < 2; r++) {
            float rmax = -1e30f;
#pragma unroll
            for (int nb = 0; nb < 8; nb++)
                rmax = fmaxf(rmax, fmaxf(sacc[nb][2 * r], sacc[nb][2 * r + 1]));
            rmax = fmaxf(rmax, __shfl_xor_sync(0xffffffffu, rmax, 1));
            rmax = fmaxf(rmax, __shfl_xor_sync(0xffffffffu, rmax, 2));
            float nm = fmaxf(m[r], rmax);
            float corr = __expf(m[r] - nm);
            float rs = 0.f;
#pragma unroll
            for (int nb = 0; nb < 8; nb++) {
                float p0 = __expf(sacc[nb][2 * r]     - nm);
                float p1 = __expf(sacc[nb][2 * r + 1] - nm);
                sacc[nb][2 * r] = p0; sacc[nb][2 * r + 1] = p1;
                rs += p0 + p1;
            }
            rs += __shfl_xor_sync(0xffffffffu, rs, 1);
            rs += __shfl_xor_sync(0xffffffffu, rs, 2);
            m[r] = nm;
            l[r] = l[r] * corr + rs;
#pragma unroll
            for (int nb = 0; nb < 16; nb++) {
                oacc[nb][2 * r]     *= corr;
                oacc[nb][2 * r + 1] *= corr;
            }
        }

#pragma unroll
        for (int nb = 0; nb < 8; nb++) {
            int c = nb * 8 + 2 * tig;
            Ps[(qrow + gid)     * PS_STR + c]     = f2tf32(sacc[nb][0]);
            Ps[(qrow + gid)     * PS_STR + c + 1] = f2tf32(sacc[nb][1]);
            Ps[(qrow + gid + 8) * PS_STR + c]     = f2tf32(sacc[nb][2]);
            Ps[(qrow + gid + 8) * PS_STR + c + 1] = f2tf32(sacc[nb][3]);
        }

#pragma unroll
        for (int kb = 0; kb < 8; kb++) {
            const int k0 = kb * 8;
            uint32_t a[4];
            a[0] = Ps[(qrow + gid)     * PS_STR + k0 + tig];
            a[1] = Ps[(qrow + gid + 8) * PS_STR + k0 + tig];
            a[2] = Ps[(qrow + gid)     * PS_STR + k0 + tig + 4];
            a[3] = Ps[(qrow + gid + 8) * PS_STR + k0 + tig + 4];
#pragma unroll
            for (int nb = 0; nb < 16; nb++) {
                uint32_t bb[2];
                bb[0] = Vs[(k0 + tig)     * VS_STR + nb * 8 + gid];
                bb[1] = Vs[(k0 + tig + 4) * VS_STR + nb * 8 + gid];
                MMA_TF32(oacc[nb], a, bb);
            }
        }
    }

    const float inv0 = 1.f / l[0];
    const float inv1 = 1.f / l[1];
    const int t0 = b * SEQ + q0 + qrow + gid;
#pragma unroll
    for (int nb = 0; nb < 16; nb++) {
        int c = nb * 8 + 2 * tig;
        float2 v0 = {oacc[nb][0] * inv0, oacc[nb][1] * inv0};
        float2 v1 = {oacc[nb][2] * inv1, oacc[nb][3] * inv1};
        *reinterpret_cast<float2*>(out + (size_t)t0 * (NH * HDIM) + h * HDIM + c) = v0;
        *reinterpret_cast<float2*>(out + (size_t)(t0 + 8) * (NH * HDIM) + h * HDIM + c) = v1;
    }
}

// ---------------------------------------------------------------------------
extern "C" void kernel_launch(void* const* d_in, const int* in_sizes, int n_in,
                              void* d_out, int out_size) {
    const float* hidden = (const float*)d_in[0];
    const float* w_qkv  = (const float*)d_in[1];
    const float* cosT   = (const float*)d_in[2];
    const float* sinT   = (const float*)d_in[3];
    float* out = (float*)d_out;

    cudaFuncSetAttribute(gemm_tf32_kernel, cudaFuncAttributeMaxDynamicSharedMemorySize, 98304);
    cudaFuncSetAttribute(attn_tc_kernel, cudaFuncAttributeMaxDynamicSharedMemorySize, ATTN_SMEM);

    pack_a_kernel<<<(T_TOK * DMODEL / 4) / 256, 256>>>(hidden);
    pack_w_kernel<<<(DMODEL * QKVC / 4) / 256, 256>>>(w_qkv);

    dim3 ggrid(QKVC / 128, T_TOK / 128);   // (48, 16)
    gemm_tf32_kernel<<<ggrid, 256, 98304>>>();

    int rope_threads = T_TOK * (NH + NKV) * 64;
    rope_kernel<<<rope_threads / 256, 256>>>(cosT, sinT);

    dim3 agrid(SEQ / 128, NBATCH * NH);    // (8, 64)
    attn_tc_kernel<<<agrid, 256, ATTN_SMEM>>>(out);
}

// round 9
// speedup vs baseline: 1.7323x; 1.4856x over previous
#include <cuda_runtime.h>
#include <cuda_fp16.h>
#include <cstdint>

// Problem constants (B=2, S=1024, H=32, KVH=8, HD=128, DM=4096)
#define T_TOK   2048
#define DMODEL  4096
#define QKVC    6144
#define NH      32
#define NKV     8
#define HDIM    128
#define SEQ     1024
#define NBATCH  2
#define QSCALE  0.08838834764831845f

__device__ float g_qkv[(size_t)T_TOK * QKVC];
__device__ uint32_t g_pa[(size_t)T_TOK * DMODEL / 2];   // packed fp16 A tiles
__device__ uint32_t g_pb[(size_t)QKVC * DMODEL / 2];    // packed fp16 W tiles

__device__ __forceinline__ uint32_t f2tf32(float x) {
    uint32_t u;
    asm("cvt.rna.tf32.f32 %0, %1;" : "=r"(u) : "f"(x));
    return u;
}
__device__ __forceinline__ uint32_t pack_h2(float lo, float hi) {
    __half2 h = __floats2half2_rn(lo, hi);
    return *reinterpret_cast<uint32_t*>(&h);
}

// fp16 k16 MMA: A 4 regs (half2 each), B 2 regs, D fp32 x4.
#define MMA_F16(d, a, b)                                                      \
    asm volatile(                                                             \
        "mma.sync.aligned.m16n8k16.row.col.f32.f16.f16.f32 "                  \
        "{%0,%1,%2,%3},{%4,%5,%6,%7},{%8,%9},{%0,%1,%2,%3};"                  \
        : "+f"(d[0]), "+f"(d[1]), "+f"(d[2]), "+f"(d[3])                      \
        : "r"(a[0]), "r"(a[1]), "r"(a[2]), "r"(a[3]), "r"(b[0]), "r"(b[1]))

// tf32 k8 MMA (attention, unchanged).
#define MMA_TF32(d, a, b)                                                     \
    asm volatile(                                                             \
        "mma.sync.aligned.m16n8k8.row.col.f32.tf32.tf32.f32 "                 \
        "{%0,%1,%2,%3},{%4,%5,%6,%7},{%8,%9},{%0,%1,%2,%3};"                  \
        : "+f"(d[0]), "+f"(d[1]), "+f"(d[2]), "+f"(d[3])                      \
        : "r"(a[0]), "r"(a[1]), "r"(a[2]), "r"(a[3]), "r"(b[0]), "r"(b[1]))

__device__ __forceinline__ void cp_async16(uint32_t smem_addr, const void* gptr) {
    asm volatile("cp.async.cg.shared.global [%0], [%1], 16;"
                 :: "r"(smem_addr), "l"(gptr) : "memory");
}
#define CP_COMMIT() asm volatile("cp.async.commit_group;" ::: "memory")
#define CP_WAIT1()  asm volatile("cp.async.wait_group 1;" ::: "memory")

// ---------------------------------------------------------------------------
// Kernel 0a: pack A [2048,4096] fp32 -> g_pa fp16 fragment-major tiles.
// A ktile (128 rows x 16 k) = 1024 words: word = rb*128 + lane*4 + reg
//   element (r16, kc): lane=(r16&7)*4+((kc>>1)&3); reg=(kc>=8)*2+(r16>=8);
//   word packs halves (kc even, kc odd).
// ---------------------------------------------------------------------------
__global__ __launch_bounds__(256) void pack_a_kernel(const float* __restrict__ A) {
    int i = blockIdx.x * 256 + threadIdx.x;
    int r  = i >> 10;
    int k0 = (i & 1023) << 2;                     // 4 consecutive k
    float4 v = *reinterpret_cast<const float4*>(A + (size_t)r * DMODEL + k0);

    int mTile = r >> 7, rLoc = r & 127;
    int kTile = k0 >> 4, kLoc = k0 & 15;          // 0,4,8,12
    uint32_t* dst = g_pa + ((size_t)(mTile * (DMODEL / 16) + kTile)) * 1024;

    int rb = rLoc >> 4, r16 = rLoc & 15;
    int reg = ((kLoc >= 8) ? 2 : 0) + ((r16 >= 8) ? 1 : 0);
    int lane0 = (r16 & 7) * 4 + ((kLoc >> 1) & 3);
    int base = rb * 128;
    dst[base + lane0 * 4 + reg]       = pack_h2(v.x, v.y);
    dst[base + (lane0 + 1) * 4 + reg] = pack_h2(v.z, v.w);
}

// ---------------------------------------------------------------------------
// Kernel 0b: pack W [4096,6144] fp32 -> g_pb fp16 fragment-major tiles.
// B ktile (128 n x 16 k) = 1024 words: word = nblk*64 + lane*2 + reg
//   element (kc, n): lane=(n&7)*4+((kc>>1)&3); reg=(kc>=8); half=kc&1.
// Thread reads 2 k-rows x 4 n -> 4 full half2 words.
// ---------------------------------------------------------------------------
__global__ __launch_bounds__(256) void pack_w_kernel(const float* __restrict__ W) {
    int i = blockIdx.x * 256 + threadIdx.x;       // (kpair, n0) pairs
    int kp = i / 1536;                            // 0..2047 (k = 2*kp)
    int n0 = (i - kp * 1536) << 2;
    int k  = kp * 2;
    float4 vlo = *reinterpret_cast<const float4*>(W + (size_t)k * QKVC + n0);
    float4 vhi = *reinterpret_cast<const float4*>(W + (size_t)(k + 1) * QKVC + n0);

    int nTile = n0 >> 7, nLoc0 = n0 & 127;
    int kTile = k >> 4,  kLoc  = k & 15;          // even
    uint32_t* dst = g_pb + ((size_t)(nTile * (DMODEL / 16) + kTile)) * 1024;

    int tig = (kLoc >> 1) & 3;
    int reg = (kLoc >= 8) ? 1 : 0;
    float lo[4] = {vlo.x, vlo.y, vlo.z, vlo.w};
    float hi[4] = {vhi.x, vhi.y, vhi.z, vhi.w};
#pragma unroll
    for (int j = 0; j < 4; j++) {
        int n = nLoc0 + j;
        int nblk = n >> 3, nn = n & 7;
        dst[nblk * 64 + (nn * 4 + tig) * 2 + reg] = pack_h2(lo[j], hi[j]);
    }
}

// ---------------------------------------------------------------------------
// Kernel 1: QKV GEMM, fp16 mma.sync m16n8k16, pre-packed operands.
// CTA 128x128, 256 threads (8 warps 2x4), warp tile 64x32.
// BK=32 chunk = 2 ktiles; stage = 16KB; 3 stages = 48KB dynamic.
// ---------------------------------------------------------------------------
__global__ __launch_bounds__(256, 2) void gemm_f16_kernel() {
    extern __shared__ __align__(16) uint32_t smem[];   // 3 * 4096 words

    const int tid  = threadIdx.x;
    const int wid  = tid >> 5;
    const int lane = tid & 31;
    const int gid  = lane >> 2;
    const int tig  = lane & 3;
    const int wm   = wid >> 2;
    const int wn   = wid & 3;

    const uint32_t smem_base = (uint32_t)__cvta_generic_to_shared(smem);
    const uint32_t* pa = g_pa + (size_t)blockIdx.y * (DMODEL / 16) * 1024;
    const uint32_t* pb = g_pb + (size_t)blockIdx.x * (DMODEL / 16) * 1024;

    const int NCH = DMODEL / 32;   // 128 BK32 chunks

    // Stage layout (words): [A kt0 1024][A kt1 1024][B kt0 1024][B kt1 1024]
#define ISSUE(ch, s)                                                           \
    do {                                                                       \
        uint32_t sa = smem_base + (uint32_t)(s) * 16384;                       \
        const uint32_t* gA = pa + (size_t)(ch) * 2048 + tid * 4;               \
        const uint32_t* gB = pb + (size_t)(ch) * 2048 + tid * 4;               \
        cp_async16(sa + tid * 16,          gA);                                \
        cp_async16(sa + tid * 16 + 4096,   gA + 1024);                         \
        cp_async16(sa + 8192 + tid * 16,        gB);                           \
        cp_async16(sa + 8192 + tid * 16 + 4096, gB + 1024);                    \
    } while (0)

    float acc[4][4][4];
#pragma unroll
    for (int i = 0; i < 4; i++)
#pragma unroll
        for (int j = 0; j < 4; j++)
#pragma unroll
            for (int c = 0; c < 4; c++) acc[i][j][c] = 0.f;

    ISSUE(0, 0); CP_COMMIT();
    ISSUE(1, 1); CP_COMMIT();
    CP_WAIT1();
    __syncthreads();

    for (int ch = 0; ch < NCH; ch++) {
        if (ch + 2 < NCH) ISSUE(ch + 2, (ch + 2) % 3);
        CP_COMMIT();

        const uint32_t* St = smem + (size_t)(ch % 3) * 4096;

#pragma unroll
        for (int kt = 0; kt < 2; kt++) {           // two k16 steps per chunk
            const uint32_t* As = St + kt * 1024;
            const uint32_t* Bs = St + 2048 + kt * 1024;
            uint4 av[4];
            uint2 bv[4];
#pragma unroll
            for (int i = 0; i < 4; i++)
                av[i] = *reinterpret_cast<const uint4*>(
                    &As[((wm << 2) + i) * 128 + (lane << 2)]);
#pragma unroll
            for (int j = 0; j < 4; j++)
                bv[j] = *reinterpret_cast<const uint2*>(
                    &Bs[((wn << 2) + j) * 64 + (lane << 1)]);
#pragma unroll
            for (int i = 0; i < 4; i++)
#pragma unroll
                for (int j = 0; j < 4; j++)
                    MMA_F16(acc[i][j], (reinterpret_cast<uint32_t*>(&av[i])),
                            (reinterpret_cast<uint32_t*>(&bv[j])));
        }

        CP_WAIT1();
        __syncthreads();
    }

    // Epilogue.
    float* C = g_qkv + (size_t)blockIdx.y * 128 * QKVC + blockIdx.x * 128;
#pragma unroll
    for (int i = 0; i < 4; i++) {
#pragma unroll
        for (int j = 0; j < 4; j++) {
            int r = wm * 64 + i * 16 + gid;
            int c = wn * 32 + j * 8 + 2 * tig;
            float2 v0 = {acc[i][j][0], acc[i][j][1]};
            float2 v1 = {acc[i][j][2], acc[i][j][3]};
            *reinterpret_cast<float2*>(C + (size_t)(r)     * QKVC + c) = v0;
            *reinterpret_cast<float2*>(C + (size_t)(r + 8) * QKVC + c) = v1;
        }
    }
}

// ---------------------------------------------------------------------------
// Kernel 2: RoPE in-place (q scaled by 1/sqrt(HD)).
// ---------------------------------------------------------------------------
__global__ __launch_bounds__(256) void rope_kernel(const float* __restrict__ cosT,
                                                   const float* __restrict__ sinT) {
    int idx = blockIdx.x * 256 + threadIdx.x;
    int d    = idx & 63;
    int head = (idx >> 6) % 40;
    int t    = idx / (64 * 40);

    float c = cosT[t * HDIM + d];
    float s = sinT[t * HDIM + d];

    float* p = g_qkv + (size_t)t * QKVC + head * HDIM;
    float x1 = p[d];
    float x2 = p[d + 64];
    float o1 = x1 * c - x2 * s;
    float o2 = x2 * c + x1 * s;
    if (head < NH) { o1 *= QSCALE; o2 *= QSCALE; }
    p[d]      = o1;
    p[d + 64] = o2;
}

// ---------------------------------------------------------------------------
// Kernel 3: tensor-core flash attention (causal, GQA n_rep=4), tf32 mma.
// (unchanged from R6/R8 best)
// ---------------------------------------------------------------------------
#define QS_STR 132
#define KS_STR 132
#define VS_STR 136
#define PS_STR 68
#define QS_WORDS (128 * QS_STR)
#define KS_WORDS (64 * KS_STR)
#define VS_WORDS (64 * VS_STR)
#define PS_WORDS (128 * PS_STR)
#define ATTN_SMEM ((QS_WORDS + KS_WORDS + VS_WORDS + PS_WORDS) * 4)

__global__ __launch_bounds__(256, 1) void attn_tc_kernel(float* __restrict__ out) {
    extern __shared__ __align__(16) uint32_t sm[];
    uint32_t* Qs = sm;
    uint32_t* Ks = Qs + QS_WORDS;
    uint32_t* Vs = Ks + KS_WORDS;
    uint32_t* Ps = Vs + VS_WORDS;

    const int tid  = threadIdx.x;
    const int wid  = tid >> 5;
    const int lane = tid & 31;
    const int gid  = lane >> 2;
    const int tig  = lane & 3;
    const int qrow = wid * 16;

    const int b   = blockIdx.y >> 5;
    const int h   = blockIdx.y & 31;
    const int kvh = h >> 2;
    const int q0  = blockIdx.x * 128;

    const float* Qg = g_qkv + (size_t)(b * SEQ + q0) * QKVC + h * HDIM;
    const float* Kg = g_qkv + (size_t)(b * SEQ) * QKVC + NH * HDIM + kvh * HDIM;
    const float* Vg = Kg + NKV * HDIM;

#pragma unroll
    for (int i = 0; i < 16; i++) {
        int idx = tid + i * 256;
        int r = idx >> 5;
        int c = (idx & 31) << 2;
        float4 v = *reinterpret_cast<const float4*>(Qg + (size_t)r * QKVC + c);
        uint32_t* d = &Qs[r * QS_STR + c];
        d[0] = f2tf32(v.x); d[1] = f2tf32(v.y); d[2] = f2tf32(v.z); d[3] = f2tf32(v.w);
    }

    float m[2] = {-1e30f, -1e30f}, l[2] = {0.f, 0.f};
    float oacc[16][4];
#pragma unroll
    for (int nb = 0; nb < 16; nb++)
#pragma unroll
        for (int c = 0; c < 4; c++) oacc[nb][c] = 0.f;

    const int ktiles = 2 * (blockIdx.x + 1);
    for (int kt = 0; kt < ktiles; kt++) {
        const int kv0 = kt * 64;
        __syncthreads();
#pragma unroll
        for (int i = 0; i < 8; i++) {
            int idx = tid + i * 256;
            int r = idx >> 5;
            int c = (idx & 31) << 2;
            float4 kv = *reinterpret_cast<const float4*>(Kg + (size_t)(kv0 + r) * QKVC + c);
            float4 vv = *reinterpret_cast<const float4*>(Vg + (size_t)(kv0 + r) * QKVC + c);
            uint32_t* dk = &Ks[r * KS_STR + c];
            dk[0] = f2tf32(kv.x); dk[1] = f2tf32(kv.y); dk[2] = f2tf32(kv.z); dk[3] = f2tf32(kv.w);
            uint32_t* dv = &Vs[r * VS_STR + c];
            dv[0] = f2tf32(vv.x); dv[1] = f2tf32(vv.y); dv[2] = f2tf32(vv.z); dv[3] = f2tf32(vv.w);
        }
        __syncthreads();

        float sacc[8][4];
#pragma unroll
        for (int nb = 0; nb < 8; nb++)
#pragma unroll
            for (int c = 0; c < 4; c++) sacc[nb][c] = 0.f;

#pragma unroll
        for (int ks = 0; ks < 16; ks++) {
            const int k0 = ks * 8;
            uint32_t a[4];
            a[0] = Qs[(qrow + gid)     * QS_STR + k0 + tig];
            a[1] = Qs[(qrow + gid + 8) * QS_STR + k0 + tig];
            a[2] = Qs[(qrow + gid)     * QS_STR + k0 + tig + 4];
            a[3] = Qs[(qrow + gid + 8) * QS_STR + k0 + tig + 4];
#pragma unroll
            for (int nb = 0; nb < 8; nb++) {
                uint32_t bb[2];
                bb[0] = Ks[(nb * 8 + gid) * KS_STR + k0 + tig];
                bb[1] = Ks[(nb * 8 + gid) * KS_STR + k0 + tig + 4];
                MMA_TF32(sacc[nb], a, bb);
            }
        }

        const int row0 = q0 + qrow + gid;
        const int row1 = row0 + 8;
        if (kv0 + 63 > row0) {
#pragma unroll
            for (int nb = 0; nb < 8; nb++) {
                int c0 = kv0 + nb * 8 + 2 * tig;
                if (c0 > row0)     sacc[nb][0] = -1e30f;
                if (c0 + 1 > row0) sacc[nb][1] = -1e30f;
                if (c0 > row1)     sacc[nb][2] = -1e30f;
                if (c0 + 1 > row1) sacc[nb][3] = -1e30f;
            }
        }

#pragma unroll
        for (int r = 0; r < 2; r++) {
            float rmax = -1e30f;
#pragma unroll
            for (int nb = 0; nb < 8; nb++)
                rmax = fmaxf(rmax, fmaxf(sacc[nb][2 * r], sacc[nb][2 * r + 1]));
            rmax = fmaxf(rmax, __shfl_xor_sync(0xffffffffu, rmax, 1));
            rmax = fmaxf(rmax, __shfl_xor_sync(0xffffffffu, rmax, 2));
            float nm = fmaxf(m[r], rmax);
            float corr = __expf(m[r] - nm);
            float rs = 0.f;
#pragma unroll
            for (int nb = 0; nb < 8; nb++) {
                float p0 = __expf(sacc[nb][2 * r]     - nm);
                float p1 = __expf(sacc[nb][2 * r + 1] - nm);
                sacc[nb][2 * r] = p0; sacc[nb][2 * r + 1] = p1;
                rs += p0 + p1;
            }
            rs += __shfl_xor_sync(0xffffffffu, rs, 1);
            rs += __shfl_xor_sync(0xffffffffu, rs, 2);
            m[r] = nm;
            l[r] = l[r] * corr + rs;
#pragma unroll
            for (int nb = 0; nb < 16; nb++) {
                oacc[nb][2 * r]     *= corr;
                oacc[nb][2 * r + 1] *= corr;
            }
        }

#pragma unroll
        for (int nb = 0; nb < 8; nb++) {
            int c = nb * 8 + 2 * tig;
            Ps[(qrow + gid)     * PS_STR + c]     = f2tf32(sacc[nb][0]);
            Ps[(qrow + gid)     * PS_STR + c + 1] = f2tf32(sacc[nb][1]);
            Ps[(qrow + gid + 8) * PS_STR + c]     = f2tf32(sacc[nb][2]);
            Ps[(qrow + gid + 8) * PS_STR + c + 1] = f2tf32(sacc[nb][3]);
        }

#pragma unroll
        for (int kb = 0; kb < 8; kb++) {
            const int k0 = kb * 8;
            uint32_t a[4];
            a[0] = Ps[(qrow + gid)     * PS_STR + k0 + tig];
            a[1] = Ps[(qrow + gid + 8) * PS_STR + k0 + tig];
            a[2] = Ps[(qrow + gid)     * PS_STR + k0 + tig + 4];
            a[3] = Ps[(qrow + gid + 8) * PS_STR + k0 + tig + 4];
#pragma unroll
            for (int nb = 0; nb < 16; nb++) {
                uint32_t bb[2];
                bb[0] = Vs[(k0 + tig)     * VS_STR + nb * 8 + gid];
                bb[1] = Vs[(k0 + tig + 4) * VS_STR + nb * 8 + gid];
                MMA_TF32(oacc[nb], a, bb);
            }
        }
    }

    const float inv0 = 1.f / l[0];
    const float inv1 = 1.f / l[1];
    const int t0 = b * SEQ + q0 + qrow + gid;
#pragma unroll
    for (int nb = 0; nb < 16; nb++) {
        int c = nb * 8 + 2 * tig;
        float2 v0 = {oacc[nb][0] * inv0, oacc[nb][1] * inv0};
        float2 v1 = {oacc[nb][2] * inv1, oacc[nb][3] * inv1};
        *reinterpret_cast<float2*>(out + (size_t)t0 * (NH * HDIM) + h * HDIM + c) = v0;
        *reinterpret_cast<float2*>(out + (size_t)(t0 + 8) * (NH * HDIM) + h * HDIM + c) = v1;
    }
}

// ---------------------------------------------------------------------------
extern "C" void kernel_launch(void* const* d_in, const int* in_sizes, int n_in,
                              void* d_out, int out_size) {
    const float* hidden = (const float*)d_in[0];
    const float* w_qkv  = (const float*)d_in[1];
    const float* cosT   = (const float*)d_in[2];
    const float* sinT   = (const float*)d_in[3];
    float* out = (float*)d_out;

    cudaFuncSetAttribute(gemm_f16_kernel, cudaFuncAttributeMaxDynamicSharedMemorySize, 49152);
    cudaFuncSetAttribute(attn_tc_kernel, cudaFuncAttributeMaxDynamicSharedMemorySize, ATTN_SMEM);

    pack_a_kernel<<<(T_TOK * DMODEL / 4) / 256, 256>>>(hidden);
    pack_w_kernel<<<(DMODEL / 2 * (QKVC / 4)) / 256, 256>>>(w_qkv);

    dim3 ggrid(QKVC / 128, T_TOK / 128);   // (48, 16)
    gemm_f16_kernel<<<ggrid, 256, 49152>>>();

    int rope_threads = T_TOK * (NH + NKV) * 64;
    rope_kernel<<<rope_threads / 256, 256>>>(cosT, sinT);

    dim3 agrid(SEQ / 128, NBATCH * NH);    // (8, 64)
    attn_tc_kernel<<<agrid, 256, ATTN_SMEM>>>(out);
}

// round 10
// speedup vs baseline: 1.7948x; 1.0361x over previous
#include <cuda_runtime.h>
#include <cuda_fp16.h>
#include <cstdint>

// Problem constants (B=2, S=1024, H=32, KVH=8, HD=128, DM=4096)
#define T_TOK   2048
#define DMODEL  4096
#define QKVC    6144
#define NH      32
#define NKV     8
#define HDIM    128
#define SEQ     1024
#define NBATCH  2
#define QSCALE  0.08838834764831845f

__device__ float g_qkv[(size_t)T_TOK * QKVC];
__device__ uint32_t g_pa[(size_t)T_TOK * DMODEL / 2];   // packed fp16 A tiles
__device__ uint32_t g_pb[(size_t)QKVC * DMODEL / 2];    // packed fp16 W tiles

__device__ __forceinline__ uint32_t pack_h2(float lo, float hi) {
    __half2 h = __floats2half2_rn(lo, hi);
    return *reinterpret_cast<uint32_t*>(&h);
}

#define MMA_F16(d, a, b)                                                      \
    asm volatile(                                                             \
        "mma.sync.aligned.m16n8k16.row.col.f32.f16.f16.f32 "                  \
        "{%0,%1,%2,%3},{%4,%5,%6,%7},{%8,%9},{%0,%1,%2,%3};"                  \
        : "+f"(d[0]), "+f"(d[1]), "+f"(d[2]), "+f"(d[3])                      \
        : "r"(a[0]), "r"(a[1]), "r"(a[2]), "r"(a[3]), "r"(b[0]), "r"(b[1]))

__device__ __forceinline__ void cp_async16(uint32_t smem_addr, const void* gptr) {
    asm volatile("cp.async.cg.shared.global [%0], [%1], 16;"
                 :: "r"(smem_addr), "l"(gptr) : "memory");
}
#define CP_COMMIT() asm volatile("cp.async.commit_group;" ::: "memory")
#define CP_WAIT1()  asm volatile("cp.async.wait_group 1;" ::: "memory")

// ---------------------------------------------------------------------------
// Kernel 0a: pack A [2048,4096] fp32 -> g_pa fp16 fragment-major tiles.
// ---------------------------------------------------------------------------
__global__ __launch_bounds__(256) void pack_a_kernel(const float* __restrict__ A) {
    int i = blockIdx.x * 256 + threadIdx.x;
    int r  = i >> 10;
    int k0 = (i & 1023) << 2;
    float4 v = *reinterpret_cast<const float4*>(A + (size_t)r * DMODEL + k0);

    int mTile = r >> 7, rLoc = r & 127;
    int kTile = k0 >> 4, kLoc = k0 & 15;
    uint32_t* dst = g_pa + ((size_t)(mTile * (DMODEL / 16) + kTile)) * 1024;

    int rb = rLoc >> 4, r16 = rLoc & 15;
    int reg = ((kLoc >= 8) ? 2 : 0) + ((r16 >= 8) ? 1 : 0);
    int lane0 = (r16 & 7) * 4 + ((kLoc >> 1) & 3);
    int base = rb * 128;
    dst[base + lane0 * 4 + reg]       = pack_h2(v.x, v.y);
    dst[base + (lane0 + 1) * 4 + reg] = pack_h2(v.z, v.w);
}

// ---------------------------------------------------------------------------
// Kernel 0b: pack W [4096,6144] fp32 -> g_pb fp16 fragment-major tiles.
// ---------------------------------------------------------------------------
__global__ __launch_bounds__(256) void pack_w_kernel(const float* __restrict__ W) {
    int i = blockIdx.x * 256 + threadIdx.x;
    int kp = i / 1536;
    int n0 = (i - kp * 1536) << 2;
    int k  = kp * 2;
    float4 vlo = *reinterpret_cast<const float4*>(W + (size_t)k * QKVC + n0);
    float4 vhi = *reinterpret_cast<const float4*>(W + (size_t)(k + 1) * QKVC + n0);

    int nTile = n0 >> 7, nLoc0 = n0 & 127;
    int kTile = k >> 4,  kLoc  = k & 15;
    uint32_t* dst = g_pb + ((size_t)(nTile * (DMODEL / 16) + kTile)) * 1024;

    int tig = (kLoc >> 1) & 3;
    int reg = (kLoc >= 8) ? 1 : 0;
    float lo[4] = {vlo.x, vlo.y, vlo.z, vlo.w};
    float hi[4] = {vhi.x, vhi.y, vhi.z, vhi.w};
#pragma unroll
    for (int j = 0; j < 4; j++) {
        int n = nLoc0 + j;
        int nblk = n >> 3, nn = n & 7;
        dst[nblk * 64 + (nn * 4 + tig) * 2 + reg] = pack_h2(lo[j], hi[j]);
    }
}

// ---------------------------------------------------------------------------
// Kernel 1: QKV GEMM, fp16 m16n8k16, pre-packed operands.
// CTA 128x128, 256 threads (8 warps 2x4), warp tile 64x32.
// BK=64 chunk = 4 ktiles; stage = 32KB; 3 stages = 96KB; 64 iterations.
// ---------------------------------------------------------------------------
__global__ __launch_bounds__(256, 2) void gemm_f16_kernel() {
    extern __shared__ __align__(16) uint32_t smem[];   // 3 * 8192 words

    const int tid  = threadIdx.x;
    const int wid  = tid >> 5;
    const int lane = tid & 31;
    const int gid  = lane >> 2;
    const int tig  = lane & 3;
    const int wm   = wid >> 2;
    const int wn   = wid & 3;

    const uint32_t smem_base = (uint32_t)__cvta_generic_to_shared(smem);
    const uint32_t* pa = g_pa + (size_t)blockIdx.y * (DMODEL / 16) * 1024;
    const uint32_t* pb = g_pb + (size_t)blockIdx.x * (DMODEL / 16) * 1024;

    const int NCH = DMODEL / 64;   // 64 BK64 chunks

    // Stage layout (words): [A kt0..kt3: 4096][B kt0..kt3: 4096]
#define ISSUE(ch, s)                                                           \
    do {                                                                       \
        uint32_t sa = smem_base + (uint32_t)(s) * 32768;                       \
        const uint32_t* gA = pa + (size_t)(ch) * 4096 + tid * 4;               \
        const uint32_t* gB = pb + (size_t)(ch) * 4096 + tid * 4;               \
        cp_async16(sa + tid * 16,           gA);                               \
        cp_async16(sa + tid * 16 + 4096,    gA + 1024);                        \
        cp_async16(sa + tid * 16 + 8192,    gA + 2048);                        \
        cp_async16(sa + tid * 16 + 12288,   gA + 3072);                        \
        cp_async16(sa + 16384 + tid * 16,         gB);                         \
        cp_async16(sa + 16384 + tid * 16 + 4096,  gB + 1024);                  \
        cp_async16(sa + 16384 + tid * 16 + 8192,  gB + 2048);                  \
        cp_async16(sa + 16384 + tid * 16 + 12288, gB + 3072);                  \
    } while (0)

    float acc[4][4][4];
#pragma unroll
    for (int i = 0; i < 4; i++)
#pragma unroll
        for (int j = 0; j < 4; j++)
#pragma unroll
            for (int c = 0; c < 4; c++) acc[i][j][c] = 0.f;

    ISSUE(0, 0); CP_COMMIT();
    ISSUE(1, 1); CP_COMMIT();
    CP_WAIT1();
    __syncthreads();

    for (int ch = 0; ch < NCH; ch++) {
        if (ch + 2 < NCH) ISSUE(ch + 2, (ch + 2) % 3);
        CP_COMMIT();

        const uint32_t* St = smem + (size_t)(ch % 3) * 8192;

#pragma unroll
        for (int kt = 0; kt < 4; kt++) {
            const uint32_t* As = St + kt * 1024;
            const uint32_t* Bs = St + 4096 + kt * 1024;
            uint4 av[4];
            uint2 bv[4];
#pragma unroll
            for (int i = 0; i < 4; i++)
                av[i] = *reinterpret_cast<const uint4*>(
                    &As[((wm << 2) + i) * 128 + (lane << 2)]);
#pragma unroll
            for (int j = 0; j < 4; j++)
                bv[j] = *reinterpret_cast<const uint2*>(
                    &Bs[((wn << 2) + j) * 64 + (lane << 1)]);
#pragma unroll
            for (int i = 0; i < 4; i++)
#pragma unroll
                for (int j = 0; j < 4; j++)
                    MMA_F16(acc[i][j], (reinterpret_cast<uint32_t*>(&av[i])),
                            (reinterpret_cast<uint32_t*>(&bv[j])));
        }

        CP_WAIT1();
        __syncthreads();
    }

    float* C = g_qkv + (size_t)blockIdx.y * 128 * QKVC + blockIdx.x * 128;
#pragma unroll
    for (int i = 0; i < 4; i++) {
#pragma unroll
        for (int j = 0; j < 4; j++) {
            int r = wm * 64 + i * 16 + gid;
            int c = wn * 32 + j * 8 + 2 * tig;
            float2 v0 = {acc[i][j][0], acc[i][j][1]};
            float2 v1 = {acc[i][j][2], acc[i][j][3]};
            *reinterpret_cast<float2*>(C + (size_t)(r)     * QKVC + c) = v0;
            *reinterpret_cast<float2*>(C + (size_t)(r + 8) * QKVC + c) = v1;
        }
    }
}

// ---------------------------------------------------------------------------
// Kernel 2: RoPE in-place (q scaled by 1/sqrt(HD)).
// ---------------------------------------------------------------------------
__global__ __launch_bounds__(256) void rope_kernel(const float* __restrict__ cosT,
                                                   const float* __restrict__ sinT) {
    int idx = blockIdx.x * 256 + threadIdx.x;
    int d    = idx & 63;
    int head = (idx >> 6) % 40;
    int t    = idx / (64 * 40);

    float c = cosT[t * HDIM + d];
    float s = sinT[t * HDIM + d];

    float* p = g_qkv + (size_t)t * QKVC + head * HDIM;
    float x1 = p[d];
    float x2 = p[d + 64];
    float o1 = x1 * c - x2 * s;
    float o2 = x2 * c + x1 * s;
    if (head < NH) { o1 *= QSCALE; o2 *= QSCALE; }
    p[d]      = o1;
    p[d + 64] = o2;
}

// ---------------------------------------------------------------------------
// Kernel 3: fp16 tensor-core flash attention (causal, GQA n_rep=4).
// CTA: 128 queries x 1 head, 256 threads (8 warps), warp owns 16 rows.
// Q in A-frag layout (8 ktiles, stride 1032); K,V in B-frag layout
// (K: 8 ktiles stride 520; V: 4 ktiles stride 1032); P as half2 [row][36].
// ---------------------------------------------------------------------------
#define AQ_WORDS (8 * 1032)    // 8256
#define AK_WORDS (8 * 520)     // 4160
#define AV_WORDS (4 * 1032)    // 4128
#define AP_WORDS (128 * 36)    // 4608
#define ATTN_SMEM ((AQ_WORDS + AK_WORDS + AV_WORDS + AP_WORDS) * 4)  // 84608

__global__ __launch_bounds__(256) void attn_tc_kernel(float* __restrict__ out) {
    extern __shared__ __align__(16) uint32_t sm[];
    uint32_t* Qs = sm;
    uint32_t* Ks = Qs + AQ_WORDS;
    uint32_t* Vs = Ks + AK_WORDS;
    uint32_t* Ps = Vs + AV_WORDS;

    const int tid  = threadIdx.x;
    const int wid  = tid >> 5;
    const int lane = tid & 31;
    const int gid  = lane >> 2;
    const int tig  = lane & 3;
    const int qrow = wid * 16;

    const int b   = blockIdx.y >> 5;
    const int h   = blockIdx.y & 31;
    const int kvh = h >> 2;
    const int q0  = blockIdx.x * 128;

    const float* Qg = g_qkv + (size_t)(b * SEQ + q0) * QKVC + h * HDIM;
    const float* Kg = g_qkv + (size_t)(b * SEQ) * QKVC + NH * HDIM + kvh * HDIM;
    const float* Vg = Kg + NKV * HDIM;

    // Load Q tile 128x128 into A-frag layout (fp16).
#pragma unroll
    for (int i = 0; i < 16; i++) {
        int idx = tid + i * 256;
        int r = idx >> 5;
        int c = (idx & 31) << 2;
        float4 v = *reinterpret_cast<const float4*>(Qg + (size_t)r * QKVC + c);
        int kTile = c >> 4, kLoc = c & 15;
        int rb = r >> 4, r16 = r & 15;
        int reg = ((kLoc >= 8) ? 2 : 0) + ((r16 >= 8) ? 1 : 0);
        int lane0 = (r16 & 7) * 4 + ((kLoc >> 1) & 3);
        uint32_t* d = &Qs[kTile * 1032 + rb * 128];
        d[lane0 * 4 + reg]       = pack_h2(v.x, v.y);
        d[(lane0 + 1) * 4 + reg] = pack_h2(v.z, v.w);
    }

    float m[2] = {-1e30f, -1e30f}, l[2] = {0.f, 0.f};
    float oacc[16][4];
#pragma unroll
    for (int nb = 0; nb < 16; nb++)
#pragma unroll
        for (int c = 0; c < 4; c++) oacc[nb][c] = 0.f;

    const int ktiles = 2 * (blockIdx.x + 1);
    for (int kt = 0; kt < ktiles; kt++) {
        const int kv0 = kt * 64;
        __syncthreads();

        // K tile 64x128 -> B-frag layout (n=kv, k=d).
#pragma unroll
        for (int i = 0; i < 8; i++) {
            int idx = tid + i * 256;
            int r = idx >> 5;                 // kv row 0..63
            int c = (idx & 31) << 2;          // d
            float4 v = *reinterpret_cast<const float4*>(Kg + (size_t)(kv0 + r) * QKVC + c);
            int kTile = c >> 4, kLoc = c & 15;
            int tig0 = (kLoc >> 1) & 3;
            int reg = (kLoc >= 8) ? 1 : 0;
            int nblk = r >> 3, nn = r & 7;
            uint32_t* d = &Ks[kTile * 520 + nblk * 64];
            d[(nn * 4 + tig0) * 2 + reg]     = pack_h2(v.x, v.y);
            d[(nn * 4 + tig0 + 1) * 2 + reg] = pack_h2(v.z, v.w);
        }
        // V tile 64x128 -> B-frag layout (n=d, k=kv): pair kv rows.
#pragma unroll
        for (int i = 0; i < 4; i++) {
            int idx = tid + i * 256;          // 1024 items
            int kvp = idx >> 5;               // kv pair 0..31
            int d0  = (idx & 31) << 2;
            int kv  = kvp * 2;
            float4 vlo = *reinterpret_cast<const float4*>(Vg + (size_t)(kv0 + kv) * QKVC + d0);
            float4 vhi = *reinterpret_cast<const float4*>(Vg + (size_t)(kv0 + kv + 1) * QKVC + d0);
            int kTile = kv >> 4, kLoc = kv & 15;
            int tg = (kLoc >> 1) & 3;
            int reg = (kLoc >= 8) ? 1 : 0;
            float lo[4] = {vlo.x, vlo.y, vlo.z, vlo.w};
            float hi[4] = {vhi.x, vhi.y, vhi.z, vhi.w};
            uint32_t* dst = &Vs[kTile * 1032];
#pragma unroll
            for (int j = 0; j < 4; j++) {
                int dd = d0 + j;
                int nblk = dd >> 3, nn = dd & 7;
                dst[nblk * 64 + (nn * 4 + tg) * 2 + reg] = pack_h2(lo[j], hi[j]);
            }
        }
        __syncthreads();

        // ---- S = Q K^T (per warp: 16 x 64), fp16 k16 ----
        float sacc[8][4];
#pragma unroll
        for (int nb = 0; nb < 8; nb++)
#pragma unroll
            for (int c = 0; c < 4; c++) sacc[nb][c] = 0.f;

#pragma unroll
        for (int ks = 0; ks < 8; ks++) {
            uint4 av = *reinterpret_cast<const uint4*>(
                &Qs[ks * 1032 + wid * 128 + (lane << 2)]);
#pragma unroll
            for (int nb = 0; nb < 8; nb++) {
                uint2 bb = *reinterpret_cast<const uint2*>(
                    &Ks[ks * 520 + nb * 64 + (lane << 1)]);
                MMA_F16(sacc[nb], (reinterpret_cast<uint32_t*>(&av)),
                        (reinterpret_cast<uint32_t*>(&bb)));
            }
        }

        // Causal mask.
        const int row0 = q0 + qrow + gid;
        const int row1 = row0 + 8;
        if (kv0 + 63 > row0) {
#pragma unroll
            for (int nb = 0; nb < 8; nb++) {
                int c0 = kv0 + nb * 8 + 2 * tig;
                if (c0 > row0)     sacc[nb][0] = -1e30f;
                if (c0 + 1 > row0) sacc[nb][1] = -1e30f;
                if (c0 > row1)     sacc[nb][2] = -1e30f;
                if (c0 + 1 > row1) sacc[nb][3] = -1e30f;
            }
        }

        // ---- online softmax (warp-private rows; quad reduction) ----
#pragma unroll
        for (int r = 0; r < 2; r++) {
            float rmax = -1e30f;
#pragma unroll
            for (int nb = 0; nb < 8; nb++)
                rmax = fmaxf(rmax, fmaxf(sacc[nb][2 * r], sacc[nb][2 * r + 1]));
            rmax = fmaxf(rmax, __shfl_xor_sync(0xffffffffu, rmax, 1));
            rmax = fmaxf(rmax, __shfl_xor_sync(0xffffffffu, rmax, 2));
            float nm = fmaxf(m[r], rmax);
            float corr = __expf(m[r] - nm);
            float rs = 0.f;
#pragma unroll
            for (int nb = 0; nb < 8; nb++) {
                float p0 = __expf(sacc[nb][2 * r]     - nm);
                float p1 = __expf(sacc[nb][2 * r + 1] - nm);
                sacc[nb][2 * r] = p0; sacc[nb][2 * r + 1] = p1;
                rs += p0 + p1;
            }
            rs += __shfl_xor_sync(0xffffffffu, rs, 1);
            rs += __shfl_xor_sync(0xffffffffu, rs, 2);
            m[r] = nm;
            l[r] = l[r] * corr + rs;
#pragma unroll
            for (int nb = 0; nb < 16; nb++) {
                oacc[nb][2 * r]     *= corr;
                oacc[nb][2 * r + 1] *= corr;
            }
        }

        // Store P as half2 words (kv pairs are already adjacent in sacc).
#pragma unroll
        for (int nb = 0; nb < 8; nb++) {
            Ps[(qrow + gid)     * 36 + nb * 4 + tig] = pack_h2(sacc[nb][0], sacc[nb][1]);
            Ps[(qrow + gid + 8) * 36 + nb * 4 + tig] = pack_h2(sacc[nb][2], sacc[nb][3]);
        }

        // ---- O += P V (per warp: 16 x 128), fp16 k16 ----
#pragma unroll
        for (int kb = 0; kb < 4; kb++) {
            uint32_t a[4];
            a[0] = Ps[(qrow + gid)     * 36 + kb * 8 + tig];
            a[1] = Ps[(qrow + gid + 8) * 36 + kb * 8 + tig];
            a[2] = Ps[(qrow + gid)     * 36 + kb * 8 + tig + 4];
            a[3] = Ps[(qrow + gid + 8) * 36 + kb * 8 + tig + 4];
#pragma unroll
            for (int nb = 0; nb < 16; nb++) {
                uint2 bb = *reinterpret_cast<const uint2*>(
                    &Vs[kb * 1032 + nb * 64 + (lane << 1)]);
                MMA_F16(oacc[nb], a, (reinterpret_cast<uint32_t*>(&bb)));
            }
        }
    }

    // Epilogue: normalize and write.
    const float inv0 = 1.f / l[0];
    const float inv1 = 1.f / l[1];
    const int t0 = b * SEQ + q0 + qrow + gid;
#pragma unroll
    for (int nb = 0; nb < 16; nb++) {
        int c = nb * 8 + 2 * tig;
        float2 v0 = {oacc[nb][0] * inv0, oacc[nb][1] * inv0};
        float2 v1 = {oacc[nb][2] * inv1, oacc[nb][3] * inv1};
        *reinterpret_cast<float2*>(out + (size_t)t0 * (NH * HDIM) + h * HDIM + c) = v0;
        *reinterpret_cast<float2*>(out + (size_t)(t0 + 8) * (NH * HDIM) + h * HDIM + c) = v1;
    }
}

// ---------------------------------------------------------------------------
extern "C" void kernel_launch(void* const* d_in, const int* in_sizes, int n_in,
                              void* d_out, int out_size) {
    const float* hidden = (const float*)d_in[0];
    const float* w_qkv  = (const float*)d_in[1];
    const float* cosT   = (const float*)d_in[2];
    const float* sinT   = (const float*)d_in[3];
    float* out = (float*)d_out;

    cudaFuncSetAttribute(gemm_f16_kernel, cudaFuncAttributeMaxDynamicSharedMemorySize, 98304);
    cudaFuncSetAttribute(attn_tc_kernel, cudaFuncAttributeMaxDynamicSharedMemorySize, ATTN_SMEM);

    pack_a_kernel<<<(T_TOK * DMODEL / 4) / 256, 256>>>(hidden);
    pack_w_kernel<<<(DMODEL / 2 * (QKVC / 4)) / 256, 256>>>(w_qkv);

    dim3 ggrid(QKVC / 128, T_TOK / 128);   // (48, 16)
    gemm_f16_kernel<<<ggrid, 256, 98304>>>();

    int rope_threads = T_TOK * (NH + NKV) * 64;
    rope_kernel<<<rope_threads / 256, 256>>>(cosT, sinT);

    dim3 agrid(SEQ / 128, NBATCH * NH);    // (8, 64)
    attn_tc_kernel<<<agrid, 256, ATTN_SMEM>>>(out);
}